// round 2
// baseline (speedup 1.0000x reference)
#include <cuda_runtime.h>
#include <cuda_bf16.h>
#include <math.h>

// Problem constants: x[B=4,S=12,N=4096,C=64], A[4096,4096], W[H=128,C=64]
#define NB 4
#define NS 12
#define BS 48          // B*S
#define NN 4096
#define CC 64
#define HH 128
#define PP (BS*CC)     // 3072  columns of GEMM1

// Scratch (allocation-free rule: device globals)
__device__ float g_d[NN];                 // rsqrt(1 + rowsum(A))
__device__ float g_xd[NN * PP];           // Xd[j][bs*64+c] = d[j]*x[b,s,j,c]  (50 MB)
__device__ float g_z [NN * PP];           // Z = A @ Xd                        (50 MB)

// ---------------------------------------------------------------------------
// 1) d[i] = rsqrt(1 + sum_j A[i,j])
// ---------------------------------------------------------------------------
__global__ void rowsum_kernel(const float* __restrict__ A) {
    const int row = blockIdx.x;
    const float4* a4 = reinterpret_cast<const float4*>(A + (size_t)row * NN);
    float s = 0.f;
    for (int i = threadIdx.x; i < NN / 4; i += blockDim.x) {
        float4 v = a4[i];
        s += (v.x + v.y) + (v.z + v.w);
    }
    __shared__ float red[8];
    for (int off = 16; off > 0; off >>= 1) s += __shfl_down_sync(0xffffffffu, s, off);
    if ((threadIdx.x & 31) == 0) red[threadIdx.x >> 5] = s;
    __syncthreads();
    if (threadIdx.x == 0) {
        float t = 0.f;
        for (int w = 0; w < (int)(blockDim.x >> 5); w++) t += red[w];
        g_d[row] = rsqrtf(t + 1.0f);
    }
}

// ---------------------------------------------------------------------------
// 2) Xd[j][bs*64+c] = d[j] * x[bs][j][c]   (float4 granularity, coalesced)
// ---------------------------------------------------------------------------
__global__ void build_xd_kernel(const float* __restrict__ x) {
    const int total4 = NN * PP / 4;        // 3,145,728
    int f = blockIdx.x * blockDim.x + threadIdx.x;
    if (f >= total4) return;
    int c4 = f & 15;                       // 64/4 = 16 float4 per (bs,j)
    int j  = (f >> 4) & (NN - 1);
    int bs = f >> 16;                      // f / (16*4096)
    float4 v = reinterpret_cast<const float4*>(x)[f];
    float dj = g_d[j];
    v.x *= dj; v.y *= dj; v.z *= dj; v.w *= dj;
    reinterpret_cast<float4*>(g_xd)[(size_t)j * (PP / 4) + bs * 16 + c4] = v;
}

// ---------------------------------------------------------------------------
// 3) GEMM1: Z[4096,3072] = A[4096,4096] @ Xd[4096,3072]  (fp32 SIMT, 128x128x8)
// ---------------------------------------------------------------------------
#define BM 128
#define BN 128
#define BK 8
__global__ void __launch_bounds__(256, 2) gemm1_kernel(const float* __restrict__ A) {
    __shared__ float As[BK][BM];   // A tile, K-major (transposed on load)
    __shared__ float Bs[BK][BN];

    const int bx = blockIdx.x;     // N tile (24)
    const int by = blockIdx.y;     // M tile (32)
    const int tid = threadIdx.x;
    const int tx = tid & 15;       // 0..15 -> N
    const int ty = tid >> 4;       // 0..15 -> M

    const float* Ap = A    + (size_t)(by * BM) * NN;
    const float* Bp = g_xd + bx * BN;

    const int arow  = tid >> 1;          // 0..127
    const int acol4 = (tid & 1) * 4;     // 0 or 4
    const int brow  = tid >> 5;          // 0..7
    const int bcol4 = (tid & 31) * 4;    // 0..124

    float acc[8][8];
    #pragma unroll
    for (int i = 0; i < 8; i++)
        #pragma unroll
        for (int j = 0; j < 8; j++) acc[i][j] = 0.f;

    #pragma unroll 4
    for (int k0 = 0; k0 < NN; k0 += BK) {
        float4 av = *reinterpret_cast<const float4*>(Ap + (size_t)arow * NN + k0 + acol4);
        float4 bv = *reinterpret_cast<const float4*>(Bp + (size_t)(k0 + brow) * PP + bcol4);
        As[acol4 + 0][arow] = av.x;
        As[acol4 + 1][arow] = av.y;
        As[acol4 + 2][arow] = av.z;
        As[acol4 + 3][arow] = av.w;
        *reinterpret_cast<float4*>(&Bs[brow][bcol4]) = bv;
        __syncthreads();

        #pragma unroll
        for (int k = 0; k < BK; k++) {
            float4 ra0 = *reinterpret_cast<const float4*>(&As[k][ty * 8]);
            float4 ra1 = *reinterpret_cast<const float4*>(&As[k][ty * 8 + 4]);
            float4 rb0 = *reinterpret_cast<const float4*>(&Bs[k][tx * 8]);
            float4 rb1 = *reinterpret_cast<const float4*>(&Bs[k][tx * 8 + 4]);
            float ra[8] = {ra0.x, ra0.y, ra0.z, ra0.w, ra1.x, ra1.y, ra1.z, ra1.w};
            float rb[8] = {rb0.x, rb0.y, rb0.z, rb0.w, rb1.x, rb1.y, rb1.z, rb1.w};
            #pragma unroll
            for (int i = 0; i < 8; i++)
                #pragma unroll
                for (int j = 0; j < 8; j++)
                    acc[i][j] = fmaf(ra[i], rb[j], acc[i][j]);
        }
        __syncthreads();
    }

    #pragma unroll
    for (int i = 0; i < 8; i++) {
        float* zrow = g_z + (size_t)(by * BM + ty * 8 + i) * PP + bx * BN + tx * 8;
        *reinterpret_cast<float4*>(zrow)     = make_float4(acc[i][0], acc[i][1], acc[i][2], acc[i][3]);
        *reinterpret_cast<float4*>(zrow + 4) = make_float4(acc[i][4], acc[i][5], acc[i][6], acc[i][7]);
    }
}

// ---------------------------------------------------------------------------
// 4) Epilogue: out[bs,i,h] = sigmoid( sum_c (x[bs,i,c] - d[i]*Z[i][bs*64+c]) * W[h,c] )
//    32 rows per block, 128 threads (one per h).
// ---------------------------------------------------------------------------
__global__ void __launch_bounds__(128) epilogue_kernel(const float* __restrict__ x,
                                                       const float* __restrict__ W,
                                                       float* __restrict__ out) {
    __shared__ float Ws[HH * (CC + 1)];   // padded rows: conflict-free
    __shared__ float ts[32][CC];

    const int tid = threadIdx.x;
    const int i0  = blockIdx.x * 32;
    const int bs  = blockIdx.y;

    for (int idx = tid; idx < HH * CC; idx += 128) {
        int h = idx >> 6, c = idx & 63;
        Ws[h * (CC + 1) + c] = W[idx];
    }
    for (int idx = tid; idx < 32 * CC; idx += 128) {
        int r = idx >> 6, c = idx & 63;
        int i = i0 + r;
        float xv = x[((size_t)bs * NN + i) * CC + c];
        float zv = g_z[(size_t)i * PP + bs * CC + c];
        ts[r][c] = xv - g_d[i] * zv;
    }
    __syncthreads();

    const int h = tid;
    const float* wrow = &Ws[h * (CC + 1)];
    for (int r = 0; r < 32; r++) {
        float acc = 0.f;
        #pragma unroll
        for (int c = 0; c < CC; c++) acc = fmaf(ts[r][c], wrow[c], acc);
        float sg = 1.0f / (1.0f + expf(-acc));
        out[((size_t)bs * NN + (i0 + r)) * HH + h] = sg;
    }
}

// ---------------------------------------------------------------------------
// 5) Copy A to output tail (reference returns (out, A))
// ---------------------------------------------------------------------------
__global__ void copyA_kernel(const float* __restrict__ A, float* __restrict__ dst) {
    int i = blockIdx.x * blockDim.x + threadIdx.x;
    const int n4 = NN * NN / 4;
    if (i < n4)
        reinterpret_cast<float4*>(dst)[i] = reinterpret_cast<const float4*>(A)[i];
}

// ---------------------------------------------------------------------------
extern "C" void kernel_launch(void* const* d_in, const int* in_sizes, int n_in,
                              void* d_out, int out_size) {
    const float* x = (const float*)d_in[0];   // [4,12,4096,64]
    const float* A = (const float*)d_in[1];   // [4096,4096]
    const float* W = (const float*)d_in[2];   // [128,64]
    float* out = (float*)d_out;

    // 1) d
    rowsum_kernel<<<NN, 256>>>(A);

    // 2) Xd
    {
        int total4 = NN * PP / 4;
        build_xd_kernel<<<(total4 + 255) / 256, 256>>>(x);
    }

    // 3) Z = A @ Xd
    {
        dim3 grid(PP / BN, NN / BM);   // (24, 32)
        gemm1_kernel<<<grid, 256>>>(A);
    }

    // 4) out = sigmoid((x - d*Z) @ W^T)
    {
        dim3 grid(NN / 32, BS);        // (128, 48)
        epilogue_kernel<<<grid, 128>>>(x, W, out);
    }

    // 5) append A
    const int out_elems = NB * NS * NN * HH;   // 25,165,824
    if (out_size >= out_elems + NN * NN) {
        int n4 = NN * NN / 4;
        copyA_kernel<<<(n4 + 255) / 256, 256>>>(A, out + out_elems);
    }
}

// round 4
// speedup vs baseline: 3.4781x; 3.4781x over previous
#include <cuda_runtime.h>
#include <cuda_bf16.h>
#include <stdint.h>
#include <math.h>

typedef unsigned int u32;
typedef unsigned long long u64;

// Problem constants: x[B=4,S=12,N=4096,C=64], A[4096,4096], W[H=128,C=64]
#define NB 4
#define NS 12
#define BS 48
#define NN 4096
#define CC 64
#define HH 128
#define PP (BS*CC)     // 3072

// Scratch (device globals; allocation-free rule)
__device__ float g_d[NN];
__device__ __nv_bfloat16 g_a16[(u64)NN * NN];     // 33.5 MB
__device__ __nv_bfloat16 g_xd16[(u64)NN * PP];    // 25 MB
__device__ float g_z[(u64)NN * PP];               // 50 MB

__device__ __forceinline__ u32 s2u(const void* p) {
    u32 r;
    asm("{.reg .u64 t; cvta.to.shared.u64 t, %1; cvt.u32.u64 %0, t;}" : "=r"(r) : "l"(p));
    return r;
}
__device__ __forceinline__ void cpasync16(u32 dst, const void* src) {
    asm volatile("cp.async.cg.shared.global [%0], [%1], 16;" :: "r"(dst), "l"(src) : "memory");
}

// ---------------------------------------------------------------------------
// 1) d[i] = rsqrt(1 + sum_j A[i,j])
// ---------------------------------------------------------------------------
__global__ void rowsum_kernel(const float* __restrict__ A) {
    const int row = blockIdx.x;
    const float4* a4 = reinterpret_cast<const float4*>(A + (u64)row * NN);
    float s = 0.f;
    for (int i = threadIdx.x; i < NN / 4; i += blockDim.x) {
        float4 v = a4[i];
        s += (v.x + v.y) + (v.z + v.w);
    }
    __shared__ float red[8];
    for (int off = 16; off > 0; off >>= 1) s += __shfl_down_sync(0xffffffffu, s, off);
    if ((threadIdx.x & 31) == 0) red[threadIdx.x >> 5] = s;
    __syncthreads();
    if (threadIdx.x == 0) {
        float t = 0.f;
        for (int w = 0; w < (int)(blockDim.x >> 5); w++) t += red[w];
        g_d[row] = rsqrtf(t + 1.0f);
    }
}

// ---------------------------------------------------------------------------
// 2a) A -> bf16
// ---------------------------------------------------------------------------
__global__ void cvtA_kernel(const float* __restrict__ A) {
    u64 i = (u64)blockIdx.x * blockDim.x + threadIdx.x;
    if (i >= (u64)NN * NN / 4) return;
    float4 v = reinterpret_cast<const float4*>(A)[i];
    __nv_bfloat162 lo = __float22bfloat162_rn(make_float2(v.x, v.y));
    __nv_bfloat162 hi = __float22bfloat162_rn(make_float2(v.z, v.w));
    uint2 o;
    o.x = *reinterpret_cast<u32*>(&lo);
    o.y = *reinterpret_cast<u32*>(&hi);
    reinterpret_cast<uint2*>(g_a16)[i] = o;
}

// ---------------------------------------------------------------------------
// 2b) Xd16[j][bs*64+c] = bf16( d[j] * x[bs][j][c] )
// ---------------------------------------------------------------------------
__global__ void build_xd16_kernel(const float* __restrict__ x) {
    const int total4 = NN * PP / 4;
    int f = blockIdx.x * blockDim.x + threadIdx.x;
    if (f >= total4) return;
    int c4 = f & 15;
    int j  = (f >> 4) & (NN - 1);
    int bs = f >> 16;
    float4 v = reinterpret_cast<const float4*>(x)[f];
    float dj = g_d[j];
    __nv_bfloat162 lo = __float22bfloat162_rn(make_float2(v.x * dj, v.y * dj));
    __nv_bfloat162 hi = __float22bfloat162_rn(make_float2(v.z * dj, v.w * dj));
    uint2 o;
    o.x = *reinterpret_cast<u32*>(&lo);
    o.y = *reinterpret_cast<u32*>(&hi);
    reinterpret_cast<uint2*>(g_xd16)[(u64)j * (PP / 4) + bs * 16 + c4] = o;
}

// ---------------------------------------------------------------------------
// 3) GEMM1: Z[4096,3072] = A16 @ Xd16   (bf16 mma.sync, fp32 accum)
//    128x128x16 tiles, 8 warps (2Mx4N), warp tile 64x32, 3-stage cp.async
// ---------------------------------------------------------------------------
#define BM 128
#define BN 128
#define BK 16
#define NSTAGE 3
#define A_BYTES (BM*BK*2)              // 4096
#define B_BYTES (BK*BN*2)              // 4096
#define STAGE_BYTES (A_BYTES + B_BYTES)

__global__ void __launch_bounds__(256, 2) gemm1_kernel() {
    __shared__ __align__(16) char smem[NSTAGE * STAGE_BYTES];
    const int tid  = threadIdx.x;
    const int lane = tid & 31, wid = tid >> 5;
    const int warpM = wid >> 2, warpN = wid & 3;     // 2 x 4 warps
    const int bx = blockIdx.x, by = blockIdx.y;
    const int bColBase = bx * BN;

    const u32 sbase = s2u(smem);

    // cp.async assignments (one 16B chunk per thread for each of A,B)
    const int am = tid >> 1, ac = tid & 1;           // A: row m (0..127), k-chunk (0..1)
    const int bk = tid >> 4, bc = tid & 15;          // B: row k (0..15), n-chunk (0..15)
    const __nv_bfloat16* Ag = g_a16  + (u64)(by * BM + am) * NN + ac * 8;
    const __nv_bfloat16* Bg = g_xd16 + (u64)bk * PP + bColBase + bc * 8;
    const u32 aDst = (u32)(am * 32)  + (u32)((ac ^ ((am >> 2) & 1)) << 4);
    const u32 bDst = (u32)A_BYTES + (u32)(bk * 256) + (u32)((bc ^ (bk & 7)) << 4);

    float acc[4][4][4];
    #pragma unroll
    for (int i = 0; i < 4; i++)
        #pragma unroll
        for (int j = 0; j < 4; j++)
            #pragma unroll
            for (int q = 0; q < 4; q++) acc[i][j][q] = 0.f;

    const int NIT = NN / BK;  // 256

    // ldmatrix lane offsets (stage-relative)
    const int lrow = lane & 15, lchunk = lane >> 4;
    u32 aOff[4], bOff[2];
    #pragma unroll
    for (int i = 0; i < 4; i++) {
        int m = warpM * 64 + i * 16 + lrow;
        aOff[i] = (u32)(m * 32) + (u32)((lchunk ^ ((m >> 2) & 1)) << 4);
    }
    #pragma unroll
    for (int j = 0; j < 2; j++) {
        int nb = warpN * 32 + j * 16;
        bOff[j] = (u32)A_BYTES + (u32)(lrow * 256)
                + (u32)((((nb >> 3) + lchunk) ^ (lrow & 7)) << 4);
    }

    // prologue: issue tiles 0 and 1
    cpasync16(sbase + 0 * STAGE_BYTES + aDst, Ag);
    cpasync16(sbase + 0 * STAGE_BYTES + bDst, Bg);
    asm volatile("cp.async.commit_group;" ::: "memory");
    cpasync16(sbase + 1 * STAGE_BYTES + aDst, Ag + BK);
    cpasync16(sbase + 1 * STAGE_BYTES + bDst, Bg + (u64)BK * PP);
    asm volatile("cp.async.commit_group;" ::: "memory");

    int stage = 0;
    for (int it = 0; it < NIT; ++it) {
        asm volatile("cp.async.wait_group 1;" ::: "memory");
        __syncthreads();
        const u32 sb = sbase + stage * STAGE_BYTES;

        u32 af[4][4];
        u32 bf[4][2];
        #pragma unroll
        for (int i = 0; i < 4; i++)
            asm volatile("ldmatrix.sync.aligned.m8n8.x4.shared.b16 {%0,%1,%2,%3}, [%4];"
                : "=r"(af[i][0]), "=r"(af[i][1]), "=r"(af[i][2]), "=r"(af[i][3])
                : "r"(sb + aOff[i]));
        #pragma unroll
        for (int j = 0; j < 2; j++) {
            u32 r0, r1, r2, r3;
            asm volatile("ldmatrix.sync.aligned.m8n8.x4.trans.shared.b16 {%0,%1,%2,%3}, [%4];"
                : "=r"(r0), "=r"(r1), "=r"(r2), "=r"(r3)
                : "r"(sb + bOff[j]));
            bf[2*j][0]   = r0; bf[2*j][1]   = r1;
            bf[2*j+1][0] = r2; bf[2*j+1][1] = r3;
        }

        #pragma unroll
        for (int i = 0; i < 4; i++)
            #pragma unroll
            for (int j = 0; j < 4; j++)
                asm volatile("mma.sync.aligned.m16n8k16.row.col.f32.bf16.bf16.f32 "
                    "{%0,%1,%2,%3}, {%4,%5,%6,%7}, {%8,%9}, {%0,%1,%2,%3};"
                    : "+f"(acc[i][j][0]), "+f"(acc[i][j][1]),
                      "+f"(acc[i][j][2]), "+f"(acc[i][j][3])
                    : "r"(af[i][0]), "r"(af[i][1]), "r"(af[i][2]), "r"(af[i][3]),
                      "r"(bf[j][0]), "r"(bf[j][1]));

        if (it + 2 < NIT) {
            int nk = (it + 2) * BK;
            int ns = stage + 2; if (ns >= NSTAGE) ns -= NSTAGE;
            const u32 sn = sbase + (u32)(ns * STAGE_BYTES);
            cpasync16(sn + aDst, Ag + nk);
            cpasync16(sn + bDst, Bg + (u64)nk * PP);
            asm volatile("cp.async.commit_group;" ::: "memory");
        }
        __syncthreads();
        if (++stage == NSTAGE) stage = 0;
    }

    // store Z (fp32)
    #pragma unroll
    for (int i = 0; i < 4; i++) {
        int r0 = by * BM + warpM * 64 + i * 16 + (lane >> 2);
        #pragma unroll
        for (int j = 0; j < 4; j++) {
            int c = bColBase + warpN * 32 + j * 8 + (lane & 3) * 2;
            *reinterpret_cast<float2*>(g_z + (u64)r0 * PP + c)
                = make_float2(acc[i][j][0], acc[i][j][1]);
            *reinterpret_cast<float2*>(g_z + (u64)(r0 + 8) * PP + c)
                = make_float2(acc[i][j][2], acc[i][j][3]);
        }
    }
}

// ---------------------------------------------------------------------------
// 4) Epilogue: out[bs,i,h] = sigmoid( sum_c (x[bs,i,c] - d[i]*Z[i][bs*64+c]) * W[h,c] )
//    W in registers (h = tid), ts read via broadcast LDS.128
// ---------------------------------------------------------------------------
__global__ void __launch_bounds__(128) epilogue_kernel(const float* __restrict__ x,
                                                       const float* __restrict__ W,
                                                       float* __restrict__ out) {
    __shared__ __align__(16) float ts[32][CC];

    const int tid = threadIdx.x;          // == h
    const int i0  = blockIdx.x * 32;
    const int bs  = blockIdx.y;

    float w[CC];
    const float4* W4 = reinterpret_cast<const float4*>(W + (u64)tid * CC);
    #pragma unroll
    for (int q = 0; q < CC / 4; q++) {
        float4 v = W4[q];
        w[4*q] = v.x; w[4*q+1] = v.y; w[4*q+2] = v.z; w[4*q+3] = v.w;
    }

    for (int idx = tid; idx < 32 * CC; idx += 128) {
        int r = idx >> 6, c = idx & 63;
        int i = i0 + r;
        float xv = x[((u64)bs * NN + i) * CC + c];
        float zv = g_z[(u64)i * PP + bs * CC + c];
        ts[r][c] = xv - g_d[i] * zv;
    }
    __syncthreads();

    #pragma unroll 2
    for (int r = 0; r < 32; r++) {
        const float4* t4 = reinterpret_cast<const float4*>(&ts[r][0]);
        float acc = 0.f;
        #pragma unroll
        for (int q = 0; q < CC / 4; q++) {
            float4 t = t4[q];   // broadcast: all lanes same address
            acc = fmaf(t.x, w[4*q], acc);
            acc = fmaf(t.y, w[4*q+1], acc);
            acc = fmaf(t.z, w[4*q+2], acc);
            acc = fmaf(t.w, w[4*q+3], acc);
        }
        float sg = 1.0f / (1.0f + __expf(-acc));
        out[((u64)bs * NN + (i0 + r)) * HH + tid] = sg;
    }
}

// ---------------------------------------------------------------------------
// 5) Copy A to output tail
// ---------------------------------------------------------------------------
__global__ void copyA_kernel(const float* __restrict__ A, float* __restrict__ dst) {
    int i = blockIdx.x * blockDim.x + threadIdx.x;
    const int n4 = NN * NN / 4;
    if (i < n4)
        reinterpret_cast<float4*>(dst)[i] = reinterpret_cast<const float4*>(A)[i];
}

// ---------------------------------------------------------------------------
extern "C" void kernel_launch(void* const* d_in, const int* in_sizes, int n_in,
                              void* d_out, int out_size) {
    const float* x = (const float*)d_in[0];
    const float* A = (const float*)d_in[1];
    const float* W = (const float*)d_in[2];
    float* out = (float*)d_out;

    rowsum_kernel<<<NN, 256>>>(A);

    {
        int n4 = NN * NN / 4;
        cvtA_kernel<<<(n4 + 255) / 256, 256>>>(A);
    }
    {
        int total4 = NN * PP / 4;
        build_xd16_kernel<<<(total4 + 255) / 256, 256>>>(x);
    }
    {
        dim3 grid(PP / BN, NN / BM);   // (24, 32)
        gemm1_kernel<<<grid, 256>>>();
    }
    {
        dim3 grid(NN / 32, BS);        // (128, 48)
        epilogue_kernel<<<grid, 128>>>(x, W, out);
    }
    const int out_elems = NB * NS * NN * HH;
    if (out_size >= out_elems + NN * NN) {
        int n4 = NN * NN / 4;
        copyA_kernel<<<(n4 + 255) / 256, 256>>>(A, out + out_elems);
    }
}

// round 7
// speedup vs baseline: 5.4084x; 1.5550x over previous
#include <cuda_runtime.h>
#include <cuda_bf16.h>
#include <stdint.h>
#include <math.h>

typedef unsigned int u32;
typedef unsigned long long u64;

// Problem constants: x[B=4,S=12,N=4096,C=64], A[4096,4096], W[H=128,C=64]
#define NB 4
#define NS 12
#define BS 48
#define NN 4096
#define CC 64
#define HH 128
#define PP (BS*CC)     // 3072

// Scratch (device globals; allocation-free rule)
__device__ float g_d[NN];
__device__ __nv_bfloat16 g_a16[(u64)NN * NN];      // A bf16 row-major (K-contig)  33.5 MB
__device__ __nv_bfloat16 g_xdT[(u64)PP * NN];      // XdT[p][k] bf16 (K-contig)    25 MB
__device__ float g_z[(u64)NN * PP];                // Z[m][p] fp32                 50 MB

__device__ __forceinline__ u32 s2u(const void* p) {
    u32 r;
    asm("{.reg .u64 t; cvta.to.shared.u64 t, %1; cvt.u32.u64 %0, t;}" : "=r"(r) : "l"(p));
    return r;
}
__device__ __forceinline__ void cpasync16(u32 dst, const void* src) {
    asm volatile("cp.async.cg.shared.global [%0], [%1], 16;" :: "r"(dst), "l"(src) : "memory");
}

// ---------------------------------------------------------------------------
// 1) Fused pass over A: rowsum->d, A->bf16, A->output tail
// ---------------------------------------------------------------------------
__global__ void __launch_bounds__(256) fusedA_kernel(const float* __restrict__ A,
                                                     float* __restrict__ outtail,
                                                     int do_copy) {
    const int row = blockIdx.x;
    const float4* a4 = reinterpret_cast<const float4*>(A + (u64)row * NN);
    float4*       o4 = reinterpret_cast<float4*>(outtail + (u64)row * NN);
    uint2*       a16 = reinterpret_cast<uint2*>(g_a16 + (u64)row * NN);

    float s = 0.f;
    for (int i = threadIdx.x; i < NN / 4; i += 256) {
        float4 v = a4[i];
        if (do_copy) o4[i] = v;
        __nv_bfloat162 lo = __float22bfloat162_rn(make_float2(v.x, v.y));
        __nv_bfloat162 hi = __float22bfloat162_rn(make_float2(v.z, v.w));
        uint2 o;
        o.x = *reinterpret_cast<u32*>(&lo);
        o.y = *reinterpret_cast<u32*>(&hi);
        a16[i] = o;
        s += (v.x + v.y) + (v.z + v.w);
    }
    __shared__ float red[8];
    for (int off = 16; off > 0; off >>= 1) s += __shfl_down_sync(0xffffffffu, s, off);
    if ((threadIdx.x & 31) == 0) red[threadIdx.x >> 5] = s;
    __syncthreads();
    if (threadIdx.x == 0) {
        float t = red[0] + red[1] + red[2] + red[3] + red[4] + red[5] + red[6] + red[7];
        g_d[row] = rsqrtf(t + 1.0f);
    }
}

// ---------------------------------------------------------------------------
// 2) XdT[p][k] = bf16( d[k] * x[bs,k,c] ),  p = bs*64+c.  SMEM transpose.
// ---------------------------------------------------------------------------
__global__ void __launch_bounds__(256) build_xdT_kernel(const float* __restrict__ x) {
    __shared__ float sm[64][65];
    const int tid = threadIdx.x;
    const int j0 = blockIdx.x * 64;
    const int bs = blockIdx.y;

    #pragma unroll
    for (int i = 0; i < 4; i++) {
        int f = tid + 256 * i;              // 0..1023 float4
        int r = f >> 4, c4 = f & 15;
        float4 v = reinterpret_cast<const float4*>(x)[((u64)bs * NN + j0 + r) * (CC / 4) + c4];
        float dj = g_d[j0 + r];
        sm[r][c4 * 4 + 0] = v.x * dj;
        sm[r][c4 * 4 + 1] = v.y * dj;
        sm[r][c4 * 4 + 2] = v.z * dj;
        sm[r][c4 * 4 + 3] = v.w * dj;
    }
    __syncthreads();

    #pragma unroll
    for (int i = 0; i < 4; i++) {
        int f = tid + 256 * i;              // 0..1023 groups of 4 bf16
        int c = f >> 4, j4 = f & 15;
        __nv_bfloat162 lo = __floats2bfloat162_rn(sm[j4 * 4 + 0][c], sm[j4 * 4 + 1][c]);
        __nv_bfloat162 hi = __floats2bfloat162_rn(sm[j4 * 4 + 2][c], sm[j4 * 4 + 3][c]);
        uint2 o;
        o.x = *reinterpret_cast<u32*>(&lo);
        o.y = *reinterpret_cast<u32*>(&hi);
        __nv_bfloat16* dst = g_xdT + (u64)(bs * 64 + c) * NN + j0 + j4 * 4;
        *reinterpret_cast<uint2*>(dst) = o;
    }
}

// ---------------------------------------------------------------------------
// 3) GEMM1: Z[4096,3072] = A16 @ XdT^T  (bf16 mma.sync, fp32 accum)
//    128x128x32 tiles, 8 warps (2Mx4N), warp tile 64x32, 3-stage cp.async
//    Both operands stored as rows of 64B (4 x 16B chunks), swizzle c^((row>>1)&3)
// ---------------------------------------------------------------------------
#define BK 32
#define NSTG 3
#define A_STG (128*64)             // 8192 B
#define B_STG (128*64)             // 8192 B
#define STG (A_STG + B_STG)        // 16384 B
#define NCHUNK (NN / BK)           // 128
#define GEMM_DYN (NSTG * STG)      // 49152 B

__device__ __forceinline__ void load_chunk(int j, int tid, u32 sbase,
                                           const __nv_bfloat16* Abase,
                                           const __nv_bfloat16* Bbase) {
    int s = j % NSTG;
    u32 sA = sbase + (u32)(s * STG);
    u32 sB = sA + A_STG;
    int k0 = j * BK;
    #pragma unroll
    for (int i = 0; i < 2; i++) {           // A: 128 rows x 4 x 16B
        int idx = tid + 256 * i;
        int row = idx >> 2, c = idx & 3;
        cpasync16(sA + (u32)(row * 64) + ((u32)(c ^ ((row >> 1) & 3)) << 4),
                  Abase + (u64)row * NN + k0 + c * 8);
    }
    #pragma unroll
    for (int i = 0; i < 2; i++) {           // B: 128 rows x 4 x 16B
        int idx = tid + 256 * i;
        int row = idx >> 2, c = idx & 3;
        cpasync16(sB + (u32)(row * 64) + ((u32)(c ^ ((row >> 1) & 3)) << 4),
                  Bbase + (u64)row * NN + k0 + c * 8);
    }
}

__global__ void __launch_bounds__(256, 2) gemm1_kernel() {
    extern __shared__ __align__(16) char dsm[];
    const int tid  = threadIdx.x;
    const int lane = tid & 31, wid = tid >> 5;
    const int warpM = wid >> 2, warpN = wid & 3;     // 2 x 4 warps
    const int bn0 = blockIdx.x * 128;
    const int bm0 = blockIdx.y * 128;

    const u32 sbase = s2u(dsm);
    const __nv_bfloat16* Abase = g_a16 + (u64)bm0 * NN;
    const __nv_bfloat16* Bbase = g_xdT + (u64)bn0 * NN;

    // ldmatrix lane offsets
    const int g = lane >> 3, lr = lane & 7;
    u32 aOff[4][2], bOff[2][2];
    #pragma unroll
    for (int i = 0; i < 4; i++) {
        int m = warpM * 64 + i * 16 + (g & 1) * 8 + lr;
        #pragma unroll
        for (int ks = 0; ks < 2; ks++) {
            int ch = 2 * ks + (g >> 1);
            aOff[i][ks] = (u32)(m * 64) + ((u32)(ch ^ ((m >> 1) & 3)) << 4);
        }
    }
    #pragma unroll
    for (int nb = 0; nb < 2; nb++) {
        int n = warpN * 32 + nb * 16 + (g >> 1) * 8 + lr;
        #pragma unroll
        for (int ks = 0; ks < 2; ks++) {
            int ch = 2 * ks + (g & 1);
            bOff[nb][ks] = (u32)A_STG + (u32)(n * 64) + ((u32)(ch ^ ((n >> 1) & 3)) << 4);
        }
    }

    float acc[4][4][4];
    #pragma unroll
    for (int i = 0; i < 4; i++)
        #pragma unroll
        for (int j = 0; j < 4; j++)
            #pragma unroll
            for (int q = 0; q < 4; q++) acc[i][j][q] = 0.f;

    // prologue: chunks 0,1
    load_chunk(0, tid, sbase, Abase, Bbase);
    asm volatile("cp.async.commit_group;" ::: "memory");
    load_chunk(1, tid, sbase, Abase, Bbase);
    asm volatile("cp.async.commit_group;" ::: "memory");

    int stage = 0;
    #pragma unroll 1
    for (int it = 0; it < NCHUNK; ++it) {
        if (it < NCHUNK - 2) asm volatile("cp.async.wait_group 1;" ::: "memory");
        else                 asm volatile("cp.async.wait_group 0;" ::: "memory");
        __syncthreads();
        const u32 sb = sbase + (u32)(stage * STG);

        #pragma unroll
        for (int ks = 0; ks < 2; ks++) {
            u32 af[4][4];
            u32 bfr[4][2];
            #pragma unroll
            for (int i = 0; i < 4; i++)
                asm volatile("ldmatrix.sync.aligned.m8n8.x4.shared.b16 {%0,%1,%2,%3}, [%4];"
                    : "=r"(af[i][0]), "=r"(af[i][1]), "=r"(af[i][2]), "=r"(af[i][3])
                    : "r"(sb + aOff[i][ks]));
            #pragma unroll
            for (int nb = 0; nb < 2; nb++) {
                u32 r0, r1, r2, r3;
                asm volatile("ldmatrix.sync.aligned.m8n8.x4.shared.b16 {%0,%1,%2,%3}, [%4];"
                    : "=r"(r0), "=r"(r1), "=r"(r2), "=r"(r3)
                    : "r"(sb + bOff[nb][ks]));
                bfr[2*nb][0]   = r0; bfr[2*nb][1]   = r1;
                bfr[2*nb+1][0] = r2; bfr[2*nb+1][1] = r3;
            }
            #pragma unroll
            for (int i = 0; i < 4; i++)
                #pragma unroll
                for (int j = 0; j < 4; j++)
                    asm volatile("mma.sync.aligned.m16n8k16.row.col.f32.bf16.bf16.f32 "
                        "{%0,%1,%2,%3}, {%4,%5,%6,%7}, {%8,%9}, {%0,%1,%2,%3};"
                        : "+f"(acc[i][j][0]), "+f"(acc[i][j][1]),
                          "+f"(acc[i][j][2]), "+f"(acc[i][j][3])
                        : "r"(af[i][0]), "r"(af[i][1]), "r"(af[i][2]), "r"(af[i][3]),
                          "r"(bfr[j][0]), "r"(bfr[j][1]));
        }

        if (it + 2 < NCHUNK) {
            load_chunk(it + 2, tid, sbase, Abase, Bbase);
            asm volatile("cp.async.commit_group;" ::: "memory");
        }
        if (++stage == NSTG) stage = 0;
    }

    // store Z (fp32)
    #pragma unroll
    for (int i = 0; i < 4; i++) {
        int r0 = bm0 + warpM * 64 + i * 16 + (lane >> 2);
        #pragma unroll
        for (int j = 0; j < 4; j++) {
            int c = bn0 + warpN * 32 + j * 8 + (lane & 3) * 2;
            *reinterpret_cast<float2*>(g_z + (u64)r0 * PP + c)
                = make_float2(acc[i][j][0], acc[i][j][1]);
            *reinterpret_cast<float2*>(g_z + (u64)(r0 + 8) * PP + c)
                = make_float2(acc[i][j][2], acc[i][j][3]);
        }
    }
}

// ---------------------------------------------------------------------------
// 4) Epilogue: out[bs,i,h] = sigmoid( sum_c (x[bs,i,c] - d[i]*Z[i][bs*64+c]) * W[h,c] )
// ---------------------------------------------------------------------------
__global__ void __launch_bounds__(128) epilogue_kernel(const float* __restrict__ x,
                                                       const float* __restrict__ W,
                                                       float* __restrict__ out) {
    __shared__ __align__(16) float ts[32][CC];

    const int tid = threadIdx.x;          // == h
    const int i0  = blockIdx.x * 32;
    const int bs  = blockIdx.y;

    float w[CC];
    const float4* W4 = reinterpret_cast<const float4*>(W + (u64)tid * CC);
    #pragma unroll
    for (int q = 0; q < CC / 4; q++) {
        float4 v = W4[q];
        w[4*q] = v.x; w[4*q+1] = v.y; w[4*q+2] = v.z; w[4*q+3] = v.w;
    }

    for (int idx = tid; idx < 32 * CC; idx += 128) {
        int r = idx >> 6, c = idx & 63;
        int i = i0 + r;
        float xv = x[((u64)bs * NN + i) * CC + c];
        float zv = g_z[(u64)i * PP + bs * CC + c];
        ts[r][c] = xv - g_d[i] * zv;
    }
    __syncthreads();

    #pragma unroll 2
    for (int r = 0; r < 32; r++) {
        const float4* t4 = reinterpret_cast<const float4*>(&ts[r][0]);
        float acc = 0.f;
        #pragma unroll
        for (int q = 0; q < CC / 4; q++) {
            float4 t = t4[q];
            acc = fmaf(t.x, w[4*q], acc);
            acc = fmaf(t.y, w[4*q+1], acc);
            acc = fmaf(t.z, w[4*q+2], acc);
            acc = fmaf(t.w, w[4*q+3], acc);
        }
        float sg = 1.0f / (1.0f + __expf(-acc));
        out[((u64)bs * NN + (i0 + r)) * HH + tid] = sg;
    }
}

// ---------------------------------------------------------------------------
extern "C" void kernel_launch(void* const* d_in, const int* in_sizes, int n_in,
                              void* d_out, int out_size) {
    const float* x = (const float*)d_in[0];
    const float* A = (const float*)d_in[1];
    const float* W = (const float*)d_in[2];
    float* out = (float*)d_out;

    const int out_elems = NB * NS * NN * HH;   // 25,165,824
    const int do_copy = (out_size >= out_elems + NN * NN) ? 1 : 0;
    float* tail = do_copy ? (out + out_elems) : (float*)g_z;

    cudaFuncSetAttribute(gemm1_kernel,
                         cudaFuncAttributeMaxDynamicSharedMemorySize, GEMM_DYN);

    fusedA_kernel<<<NN, 256>>>(A, tail, do_copy);

    {
        dim3 grid(NN / 64, BS);          // (64, 48)
        build_xdT_kernel<<<grid, 256>>>(x);
    }
    {
        dim3 grid(PP / 128, NN / 128);   // (24, 32)
        gemm1_kernel<<<grid, 256, GEMM_DYN>>>();
    }
    {
        dim3 grid(NN / 32, BS);          // (128, 48)
        epilogue_kernel<<<grid, 128>>>(x, W, out);
    }
}

// round 9
// speedup vs baseline: 5.6795x; 1.0501x over previous
#include <cuda_runtime.h>
#include <cuda_bf16.h>
#include <stdint.h>
#include <math.h>

typedef unsigned int u32;
typedef unsigned long long u64;

// Problem constants: x[B=4,S=12,N=4096,C=64], A[4096,4096], W[H=128,C=64]
#define NB 4
#define NS 12
#define BS 48
#define NN 4096
#define CC 64
#define HH 128
#define PP (BS*CC)     // 3072

// Scratch (device globals; allocation-free rule)
__device__ float g_d[NN];
__device__ __nv_bfloat16 g_a16[(u64)NN * NN];      // A bf16 row-major (K-contig)  33.5 MB
__device__ __nv_bfloat16 g_xdT[(u64)PP * NN];      // XdT[p][k] bf16 (K-contig)    25 MB
__device__ __nv_bfloat16 g_z16[(u64)NN * PP];      // Z[m][p] bf16                 25 MB

__device__ __forceinline__ u32 s2u(const void* p) {
    u32 r;
    asm("{.reg .u64 t; cvta.to.shared.u64 t, %1; cvt.u32.u64 %0, t;}" : "=r"(r) : "l"(p));
    return r;
}
__device__ __forceinline__ void cpasync16(u32 dst, const void* src) {
    asm volatile("cp.async.cg.shared.global [%0], [%1], 16;" :: "r"(dst), "l"(src) : "memory");
}
__device__ __forceinline__ u32 packbf2(float a, float b) {
    __nv_bfloat162 v = __floats2bfloat162_rn(a, b);
    return *reinterpret_cast<u32*>(&v);
}

// ---------------------------------------------------------------------------
// 1) Fused pass over A: rowsum->d, A->bf16, A->output tail
// ---------------------------------------------------------------------------
__global__ void __launch_bounds__(256) fusedA_kernel(const float* __restrict__ A,
                                                     float* __restrict__ outtail,
                                                     int do_copy) {
    const int row = blockIdx.x;
    const float4* a4 = reinterpret_cast<const float4*>(A + (u64)row * NN);
    float4*       o4 = reinterpret_cast<float4*>(outtail + (u64)row * NN);
    uint2*       a16 = reinterpret_cast<uint2*>(g_a16 + (u64)row * NN);

    float s = 0.f;
    for (int i = threadIdx.x; i < NN / 4; i += 256) {
        float4 v = a4[i];
        if (do_copy) o4[i] = v;
        uint2 o;
        o.x = packbf2(v.x, v.y);
        o.y = packbf2(v.z, v.w);
        a16[i] = o;
        s += (v.x + v.y) + (v.z + v.w);
    }
    __shared__ float red[8];
    for (int off = 16; off > 0; off >>= 1) s += __shfl_down_sync(0xffffffffu, s, off);
    if ((threadIdx.x & 31) == 0) red[threadIdx.x >> 5] = s;
    __syncthreads();
    if (threadIdx.x == 0) {
        float t = red[0] + red[1] + red[2] + red[3] + red[4] + red[5] + red[6] + red[7];
        g_d[row] = rsqrtf(t + 1.0f);
    }
}

// ---------------------------------------------------------------------------
// 2) XdT[p][k] = bf16( d[k] * x[bs,k,c] ),  p = bs*64+c.  SMEM transpose.
// ---------------------------------------------------------------------------
__global__ void __launch_bounds__(256) build_xdT_kernel(const float* __restrict__ x) {
    __shared__ float sm[64][65];
    const int tid = threadIdx.x;
    const int j0 = blockIdx.x * 64;
    const int bs = blockIdx.y;

    #pragma unroll
    for (int i = 0; i < 4; i++) {
        int f = tid + 256 * i;              // 0..1023 float4
        int r = f >> 4, c4 = f & 15;
        float4 v = reinterpret_cast<const float4*>(x)[((u64)bs * NN + j0 + r) * (CC / 4) + c4];
        float dj = g_d[j0 + r];
        sm[r][c4 * 4 + 0] = v.x * dj;
        sm[r][c4 * 4 + 1] = v.y * dj;
        sm[r][c4 * 4 + 2] = v.z * dj;
        sm[r][c4 * 4 + 3] = v.w * dj;
    }
    __syncthreads();

    #pragma unroll
    for (int i = 0; i < 4; i++) {
        int f = tid + 256 * i;              // 0..1023 groups of 4 bf16
        int c = f >> 4, j4 = f & 15;
        uint2 o;
        o.x = packbf2(sm[j4 * 4 + 0][c], sm[j4 * 4 + 1][c]);
        o.y = packbf2(sm[j4 * 4 + 2][c], sm[j4 * 4 + 3][c]);
        __nv_bfloat16* dst = g_xdT + (u64)(bs * 64 + c) * NN + j0 + j4 * 4;
        *reinterpret_cast<uint2*>(dst) = o;
    }
}

// ---------------------------------------------------------------------------
// 3) GEMM1: Z[4096,3072] = A16 @ XdT^T  (bf16 mma.sync, fp32 accum)
//    128x128x32 tiles, 8 warps (2Mx4N), 3-stage cp.async, Z stored bf16
// ---------------------------------------------------------------------------
#define BK 32
#define NSTG 3
#define A_STG (128*64)             // 8192 B
#define B_STG (128*64)             // 8192 B
#define STG (A_STG + B_STG)        // 16384 B
#define NCHUNK (NN / BK)           // 128
#define GEMM_DYN (NSTG * STG)      // 49152 B

__device__ __forceinline__ void load_chunk(int j, int tid, u32 sbase,
                                           const __nv_bfloat16* Abase,
                                           const __nv_bfloat16* Bbase) {
    int s = j % NSTG;
    u32 sA = sbase + (u32)(s * STG);
    u32 sB = sA + A_STG;
    int k0 = j * BK;
    #pragma unroll
    for (int i = 0; i < 2; i++) {           // A: 128 rows x 4 x 16B
        int idx = tid + 256 * i;
        int row = idx >> 2, c = idx & 3;
        cpasync16(sA + (u32)(row * 64) + ((u32)(c ^ ((row >> 1) & 3)) << 4),
                  Abase + (u64)row * NN + k0 + c * 8);
    }
    #pragma unroll
    for (int i = 0; i < 2; i++) {           // B: 128 rows x 4 x 16B
        int idx = tid + 256 * i;
        int row = idx >> 2, c = idx & 3;
        cpasync16(sB + (u32)(row * 64) + ((u32)(c ^ ((row >> 1) & 3)) << 4),
                  Bbase + (u64)row * NN + k0 + c * 8);
    }
}

__global__ void __launch_bounds__(256, 2) gemm1_kernel() {
    extern __shared__ __align__(16) char dsm[];
    const int tid  = threadIdx.x;
    const int lane = tid & 31, wid = tid >> 5;
    const int warpM = wid >> 2, warpN = wid & 3;     // 2 x 4 warps
    const int bn0 = blockIdx.x * 128;
    const int bm0 = blockIdx.y * 128;

    const u32 sbase = s2u(dsm);
    const __nv_bfloat16* Abase = g_a16 + (u64)bm0 * NN;
    const __nv_bfloat16* Bbase = g_xdT + (u64)bn0 * NN;

    // ldmatrix lane offsets
    const int g = lane >> 3, lr = lane & 7;
    u32 aOff[4][2], bOff[2][2];
    #pragma unroll
    for (int i = 0; i < 4; i++) {
        int m = warpM * 64 + i * 16 + (g & 1) * 8 + lr;
        #pragma unroll
        for (int ks = 0; ks < 2; ks++) {
            int ch = 2 * ks + (g >> 1);
            aOff[i][ks] = (u32)(m * 64) + ((u32)(ch ^ ((m >> 1) & 3)) << 4);
        }
    }
    #pragma unroll
    for (int nb = 0; nb < 2; nb++) {
        int n = warpN * 32 + nb * 16 + (g >> 1) * 8 + lr;
        #pragma unroll
        for (int ks = 0; ks < 2; ks++) {
            int ch = 2 * ks + (g & 1);
            bOff[nb][ks] = (u32)A_STG + (u32)(n * 64) + ((u32)(ch ^ ((n >> 1) & 3)) << 4);
        }
    }

    float acc[4][4][4];
    #pragma unroll
    for (int i = 0; i < 4; i++)
        #pragma unroll
        for (int j = 0; j < 4; j++)
            #pragma unroll
            for (int q = 0; q < 4; q++) acc[i][j][q] = 0.f;

    // prologue: chunks 0,1
    load_chunk(0, tid, sbase, Abase, Bbase);
    asm volatile("cp.async.commit_group;" ::: "memory");
    load_chunk(1, tid, sbase, Abase, Bbase);
    asm volatile("cp.async.commit_group;" ::: "memory");

    int stage = 0;
    #pragma unroll 1
    for (int it = 0; it < NCHUNK; ++it) {
        if (it < NCHUNK - 2) asm volatile("cp.async.wait_group 1;" ::: "memory");
        else                 asm volatile("cp.async.wait_group 0;" ::: "memory");
        __syncthreads();
        const u32 sb = sbase + (u32)(stage * STG);

        #pragma unroll
        for (int ks = 0; ks < 2; ks++) {
            u32 af[4][4];
            u32 bfr[4][2];
            #pragma unroll
            for (int i = 0; i < 4; i++)
                asm volatile("ldmatrix.sync.aligned.m8n8.x4.shared.b16 {%0,%1,%2,%3}, [%4];"
                    : "=r"(af[i][0]), "=r"(af[i][1]), "=r"(af[i][2]), "=r"(af[i][3])
                    : "r"(sb + aOff[i][ks]));
            #pragma unroll
            for (int nb = 0; nb < 2; nb++) {
                u32 r0, r1, r2, r3;
                asm volatile("ldmatrix.sync.aligned.m8n8.x4.shared.b16 {%0,%1,%2,%3}, [%4];"
                    : "=r"(r0), "=r"(r1), "=r"(r2), "=r"(r3)
                    : "r"(sb + bOff[nb][ks]));
                bfr[2*nb][0]   = r0; bfr[2*nb][1]   = r1;
                bfr[2*nb+1][0] = r2; bfr[2*nb+1][1] = r3;
            }
            #pragma unroll
            for (int i = 0; i < 4; i++)
                #pragma unroll
                for (int j = 0; j < 4; j++)
                    asm volatile("mma.sync.aligned.m16n8k16.row.col.f32.bf16.bf16.f32 "
                        "{%0,%1,%2,%3}, {%4,%5,%6,%7}, {%8,%9}, {%0,%1,%2,%3};"
                        : "+f"(acc[i][j][0]), "+f"(acc[i][j][1]),
                          "+f"(acc[i][j][2]), "+f"(acc[i][j][3])
                        : "r"(af[i][0]), "r"(af[i][1]), "r"(af[i][2]), "r"(af[i][3]),
                          "r"(bfr[j][0]), "r"(bfr[j][1]));
        }

        if (it + 2 < NCHUNK) {
            load_chunk(it + 2, tid, sbase, Abase, Bbase);
            asm volatile("cp.async.commit_group;" ::: "memory");
        }
        if (++stage == NSTG) stage = 0;
    }

    // store Z (bf16)
    #pragma unroll
    for (int i = 0; i < 4; i++) {
        int r0 = bm0 + warpM * 64 + i * 16 + (lane >> 2);
        #pragma unroll
        for (int j = 0; j < 4; j++) {
            int c = bn0 + warpN * 32 + j * 8 + (lane & 3) * 2;
            *reinterpret_cast<u32*>(g_z16 + (u64)r0 * PP + c)
                = packbf2(acc[i][j][0], acc[i][j][1]);
            *reinterpret_cast<u32*>(g_z16 + (u64)(r0 + 8) * PP + c)
                = packbf2(acc[i][j][2], acc[i][j][3]);
        }
    }
}

// ---------------------------------------------------------------------------
// 4) Epilogue: out[bs,i,h] = sigmoid( sum_c (x[bs,i,c] - d[i]*Z[i][bs*64+c]) * W[h,c] )
//    4 independent FMA chains per row (ILP fix), bf16 Z.
// ---------------------------------------------------------------------------
__global__ void __launch_bounds__(128) epilogue_kernel(const float* __restrict__ x,
                                                       const float* __restrict__ W,
                                                       float* __restrict__ out) {
    __shared__ __align__(16) float ts[32][CC];

    const int tid = threadIdx.x;          // == h
    const int i0  = blockIdx.x * 32;
    const int bs  = blockIdx.y;

    float w[CC];
    const float4* W4 = reinterpret_cast<const float4*>(W + (u64)tid * CC);
    #pragma unroll
    for (int q = 0; q < CC / 4; q++) {
        float4 v = W4[q];
        w[4*q] = v.x; w[4*q+1] = v.y; w[4*q+2] = v.z; w[4*q+3] = v.w;
    }

    // ts[r][c] = x - d*z  (two elems per thread-iteration)
    for (int idx = tid; idx < 32 * (CC / 2); idx += 128) {
        int r = idx >> 5, c2 = idx & 31;
        int i = i0 + r;
        float2 xv = *reinterpret_cast<const float2*>(
            x + ((u64)bs * NN + i) * CC + c2 * 2);
        u32 zr = *reinterpret_cast<const u32*>(
            g_z16 + (u64)i * PP + bs * CC + c2 * 2);
        __nv_bfloat162 z2 = *reinterpret_cast<__nv_bfloat162*>(&zr);
        float di = g_d[i];
        ts[r][c2 * 2 + 0] = xv.x - di * __bfloat162float(z2.x);
        ts[r][c2 * 2 + 1] = xv.y - di * __bfloat162float(z2.y);
    }
    __syncthreads();

    #pragma unroll 2
    for (int r = 0; r < 32; r++) {
        const float4* t4 = reinterpret_cast<const float4*>(&ts[r][0]);
        float s0 = 0.f, s1 = 0.f, s2 = 0.f, s3 = 0.f;
        #pragma unroll
        for (int q = 0; q < 16; q += 4) {
            float4 t0 = t4[q], t1 = t4[q+1], t2 = t4[q+2], t3 = t4[q+3];
            s0 = fmaf(t0.x, w[4*q+0],  s0);
            s0 = fmaf(t0.y, w[4*q+1],  s0);
            s0 = fmaf(t0.z, w[4*q+2],  s0);
            s0 = fmaf(t0.w, w[4*q+3],  s0);
            s1 = fmaf(t1.x, w[4*q+4],  s1);
            s1 = fmaf(t1.y, w[4*q+5],  s1);
            s1 = fmaf(t1.z, w[4*q+6],  s1);
            s1 = fmaf(t1.w, w[4*q+7],  s1);
            s2 = fmaf(t2.x, w[4*q+8],  s2);
            s2 = fmaf(t2.y, w[4*q+9],  s2);
            s2 = fmaf(t2.z, w[4*q+10], s2);
            s2 = fmaf(t2.w, w[4*q+11], s2);
            s3 = fmaf(t3.x, w[4*q+12], s3);
            s3 = fmaf(t3.y, w[4*q+13], s3);
            s3 = fmaf(t3.z, w[4*q+14], s3);
            s3 = fmaf(t3.w, w[4*q+15], s3);
        }
        float acc = (s0 + s1) + (s2 + s3);
        float sg = 1.0f / (1.0f + __expf(-acc));
        out[((u64)bs * NN + (i0 + r)) * HH + tid] = sg;
    }
}

// ---------------------------------------------------------------------------
extern "C" void kernel_launch(void* const* d_in, const int* in_sizes, int n_in,
                              void* d_out, int out_size) {
    const float* x = (const float*)d_in[0];
    const float* A = (const float*)d_in[1];
    const float* W = (const float*)d_in[2];
    float* out = (float*)d_out;

    const int out_elems = NB * NS * NN * HH;   // 25,165,824
    const int do_copy = (out_size >= out_elems + NN * NN) ? 1 : 0;
    float* tail = do_copy ? (out + out_elems) : (float*)g_z16;

    cudaFuncSetAttribute(gemm1_kernel,
                         cudaFuncAttributeMaxDynamicSharedMemorySize, GEMM_DYN);

    fusedA_kernel<<<NN, 256>>>(A, tail, do_copy);

    {
        dim3 grid(NN / 64, BS);          // (64, 48)
        build_xdT_kernel<<<grid, 256>>>(x);
    }
    {
        dim3 grid(PP / 128, NN / 128);   // (24, 32)
        gemm1_kernel<<<grid, 256, GEMM_DYN>>>();
    }
    {
        dim3 grid(NN / 32, BS);          // (128, 48)
        epilogue_kernel<<<grid, 128>>>(x, W, out);
    }
}

// round 11
// speedup vs baseline: 7.1046x; 1.2509x over previous
#include <cuda_runtime.h>
#include <cuda_bf16.h>
#include <stdint.h>
#include <math.h>

typedef unsigned int u32;
typedef unsigned long long u64;

// Problem constants: x[B=4,S=12,N=4096,C=64], A[4096,4096], W[H=128,C=64]
#define NB 4
#define NS 12
#define BS 48
#define NN 4096
#define CC 64
#define HH 128
#define PP (BS*CC)     // 3072

// Scratch (device globals; allocation-free rule)
__device__ float g_d[NN];
__device__ __nv_bfloat16 g_a16[(u64)NN * NN];      // A bf16 row-major (K-contig)  33.5 MB
__device__ __nv_bfloat16 g_xdT[(u64)PP * NN];      // XdT[p][k] bf16 (K-contig)    25 MB
__device__ __nv_bfloat16 g_z16[(u64)NN * PP];      // Z[m][p] bf16                 25 MB

__device__ __forceinline__ u32 s2u(const void* p) {
    u32 r;
    asm("{.reg .u64 t; cvta.to.shared.u64 t, %1; cvt.u32.u64 %0, t;}" : "=r"(r) : "l"(p));
    return r;
}
__device__ __forceinline__ void cpasync16(u32 dst, const void* src) {
    asm volatile("cp.async.cg.shared.global [%0], [%1], 16;" :: "r"(dst), "l"(src) : "memory");
}
__device__ __forceinline__ u32 packbf2(float a, float b) {
    __nv_bfloat162 v = __floats2bfloat162_rn(a, b);
    return *reinterpret_cast<u32*>(&v);
}
__device__ __forceinline__ u32 f2tf32(float f) {
    u32 r;
    asm("cvt.rna.tf32.f32 %0, %1;" : "=r"(r) : "f"(f));
    return r;
}

// ---------------------------------------------------------------------------
// 1) Fused pass over A: rowsum->d, A->bf16, A->output tail
// ---------------------------------------------------------------------------
__global__ void __launch_bounds__(256) fusedA_kernel(const float* __restrict__ A,
                                                     float* __restrict__ outtail,
                                                     int do_copy) {
    const int row = blockIdx.x;
    const float4* a4 = reinterpret_cast<const float4*>(A + (u64)row * NN);
    float4*       o4 = reinterpret_cast<float4*>(outtail + (u64)row * NN);
    uint2*       a16 = reinterpret_cast<uint2*>(g_a16 + (u64)row * NN);

    float s = 0.f;
    for (int i = threadIdx.x; i < NN / 4; i += 256) {
        float4 v = a4[i];
        if (do_copy) o4[i] = v;
        uint2 o;
        o.x = packbf2(v.x, v.y);
        o.y = packbf2(v.z, v.w);
        a16[i] = o;
        s += (v.x + v.y) + (v.z + v.w);
    }
    __shared__ float red[8];
    for (int off = 16; off > 0; off >>= 1) s += __shfl_down_sync(0xffffffffu, s, off);
    if ((threadIdx.x & 31) == 0) red[threadIdx.x >> 5] = s;
    __syncthreads();
    if (threadIdx.x == 0) {
        float t = red[0] + red[1] + red[2] + red[3] + red[4] + red[5] + red[6] + red[7];
        g_d[row] = rsqrtf(t + 1.0f);
    }
}

// ---------------------------------------------------------------------------
// 2) XdT[p][k] = bf16( d[k] * x[bs,k,c] ),  p = bs*64+c.  SMEM transpose.
// ---------------------------------------------------------------------------
__global__ void __launch_bounds__(256) build_xdT_kernel(const float* __restrict__ x) {
    __shared__ float sm[64][65];
    const int tid = threadIdx.x;
    const int j0 = blockIdx.x * 64;
    const int bs = blockIdx.y;

    #pragma unroll
    for (int i = 0; i < 4; i++) {
        int f = tid + 256 * i;              // 0..1023 float4
        int r = f >> 4, c4 = f & 15;
        float4 v = reinterpret_cast<const float4*>(x)[((u64)bs * NN + j0 + r) * (CC / 4) + c4];
        float dj = g_d[j0 + r];
        sm[r][c4 * 4 + 0] = v.x * dj;
        sm[r][c4 * 4 + 1] = v.y * dj;
        sm[r][c4 * 4 + 2] = v.z * dj;
        sm[r][c4 * 4 + 3] = v.w * dj;
    }
    __syncthreads();

    #pragma unroll
    for (int i = 0; i < 4; i++) {
        int f = tid + 256 * i;              // 0..1023 groups of 4 bf16
        int c = f >> 4, j4 = f & 15;
        uint2 o;
        o.x = packbf2(sm[j4 * 4 + 0][c], sm[j4 * 4 + 1][c]);
        o.y = packbf2(sm[j4 * 4 + 2][c], sm[j4 * 4 + 3][c]);
        __nv_bfloat16* dst = g_xdT + (u64)(bs * 64 + c) * NN + j0 + j4 * 4;
        *reinterpret_cast<uint2*>(dst) = o;
    }
}

// ---------------------------------------------------------------------------
// 3) GEMM1: Z[4096,3072] = A16 @ XdT^T  (bf16 mma.sync, fp32 accum)
//    128x128x32 tiles, 8 warps (2Mx4N), 3-stage cp.async, Z stored bf16
// ---------------------------------------------------------------------------
#define BK 32
#define NSTG 3
#define A_STG (128*64)             // 8192 B
#define B_STG (128*64)             // 8192 B
#define STG (A_STG + B_STG)        // 16384 B
#define NCHUNK (NN / BK)           // 128
#define GEMM_DYN (NSTG * STG)      // 49152 B

__device__ __forceinline__ void load_chunk(int j, int tid, u32 sbase,
                                           const __nv_bfloat16* Abase,
                                           const __nv_bfloat16* Bbase) {
    int s = j % NSTG;
    u32 sA = sbase + (u32)(s * STG);
    u32 sB = sA + A_STG;
    int k0 = j * BK;
    #pragma unroll
    for (int i = 0; i < 2; i++) {           // A: 128 rows x 4 x 16B
        int idx = tid + 256 * i;
        int row = idx >> 2, c = idx & 3;
        cpasync16(sA + (u32)(row * 64) + ((u32)(c ^ ((row >> 1) & 3)) << 4),
                  Abase + (u64)row * NN + k0 + c * 8);
    }
    #pragma unroll
    for (int i = 0; i < 2; i++) {           // B: 128 rows x 4 x 16B
        int idx = tid + 256 * i;
        int row = idx >> 2, c = idx & 3;
        cpasync16(sB + (u32)(row * 64) + ((u32)(c ^ ((row >> 1) & 3)) << 4),
                  Bbase + (u64)row * NN + k0 + c * 8);
    }
}

__global__ void __launch_bounds__(256, 2) gemm1_kernel() {
    extern __shared__ __align__(16) char dsm[];
    const int tid  = threadIdx.x;
    const int lane = tid & 31, wid = tid >> 5;
    const int warpM = wid >> 2, warpN = wid & 3;     // 2 x 4 warps
    const int bn0 = blockIdx.x * 128;
    const int bm0 = blockIdx.y * 128;

    const u32 sbase = s2u(dsm);
    const __nv_bfloat16* Abase = g_a16 + (u64)bm0 * NN;
    const __nv_bfloat16* Bbase = g_xdT + (u64)bn0 * NN;

    // ldmatrix lane offsets
    const int g = lane >> 3, lr = lane & 7;
    u32 aOff[4][2], bOff[2][2];
    #pragma unroll
    for (int i = 0; i < 4; i++) {
        int m = warpM * 64 + i * 16 + (g & 1) * 8 + lr;
        #pragma unroll
        for (int ks = 0; ks < 2; ks++) {
            int ch = 2 * ks + (g >> 1);
            aOff[i][ks] = (u32)(m * 64) + ((u32)(ch ^ ((m >> 1) & 3)) << 4);
        }
    }
    #pragma unroll
    for (int nb = 0; nb < 2; nb++) {
        int n = warpN * 32 + nb * 16 + (g >> 1) * 8 + lr;
        #pragma unroll
        for (int ks = 0; ks < 2; ks++) {
            int ch = 2 * ks + (g & 1);
            bOff[nb][ks] = (u32)A_STG + (u32)(n * 64) + ((u32)(ch ^ ((n >> 1) & 3)) << 4);
        }
    }

    float acc[4][4][4];
    #pragma unroll
    for (int i = 0; i < 4; i++)
        #pragma unroll
        for (int j = 0; j < 4; j++)
            #pragma unroll
            for (int q = 0; q < 4; q++) acc[i][j][q] = 0.f;

    // prologue: chunks 0,1
    load_chunk(0, tid, sbase, Abase, Bbase);
    asm volatile("cp.async.commit_group;" ::: "memory");
    load_chunk(1, tid, sbase, Abase, Bbase);
    asm volatile("cp.async.commit_group;" ::: "memory");

    int stage = 0;
    #pragma unroll 1
    for (int it = 0; it < NCHUNK; ++it) {
        if (it < NCHUNK - 2) asm volatile("cp.async.wait_group 1;" ::: "memory");
        else                 asm volatile("cp.async.wait_group 0;" ::: "memory");
        __syncthreads();
        const u32 sb = sbase + (u32)(stage * STG);

        #pragma unroll
        for (int ks = 0; ks < 2; ks++) {
            u32 af[4][4];
            u32 bfr[4][2];
            #pragma unroll
            for (int i = 0; i < 4; i++)
                asm volatile("ldmatrix.sync.aligned.m8n8.x4.shared.b16 {%0,%1,%2,%3}, [%4];"
                    : "=r"(af[i][0]), "=r"(af[i][1]), "=r"(af[i][2]), "=r"(af[i][3])
                    : "r"(sb + aOff[i][ks]));
            #pragma unroll
            for (int nb = 0; nb < 2; nb++) {
                u32 r0, r1, r2, r3;
                asm volatile("ldmatrix.sync.aligned.m8n8.x4.shared.b16 {%0,%1,%2,%3}, [%4];"
                    : "=r"(r0), "=r"(r1), "=r"(r2), "=r"(r3)
                    : "r"(sb + bOff[nb][ks]));
                bfr[2*nb][0]   = r0; bfr[2*nb][1]   = r1;
                bfr[2*nb+1][0] = r2; bfr[2*nb+1][1] = r3;
            }
            #pragma unroll
            for (int i = 0; i < 4; i++)
                #pragma unroll
                for (int j = 0; j < 4; j++)
                    asm volatile("mma.sync.aligned.m16n8k16.row.col.f32.bf16.bf16.f32 "
                        "{%0,%1,%2,%3}, {%4,%5,%6,%7}, {%8,%9}, {%0,%1,%2,%3};"
                        : "+f"(acc[i][j][0]), "+f"(acc[i][j][1]),
                          "+f"(acc[i][j][2]), "+f"(acc[i][j][3])
                        : "r"(af[i][0]), "r"(af[i][1]), "r"(af[i][2]), "r"(af[i][3]),
                          "r"(bfr[j][0]), "r"(bfr[j][1]));
        }

        if (it + 2 < NCHUNK) {
            load_chunk(it + 2, tid, sbase, Abase, Bbase);
            asm volatile("cp.async.commit_group;" ::: "memory");
        }
        if (++stage == NSTG) stage = 0;
    }

    // store Z (bf16)
    #pragma unroll
    for (int i = 0; i < 4; i++) {
        int r0 = bm0 + warpM * 64 + i * 16 + (lane >> 2);
        #pragma unroll
        for (int j = 0; j < 4; j++) {
            int c = bn0 + warpN * 32 + j * 8 + (lane & 3) * 2;
            *reinterpret_cast<u32*>(g_z16 + (u64)r0 * PP + c)
                = packbf2(acc[i][j][0], acc[i][j][1]);
            *reinterpret_cast<u32*>(g_z16 + (u64)(r0 + 8) * PP + c)
                = packbf2(acc[i][j][2], acc[i][j][3]);
        }
    }
}

// ---------------------------------------------------------------------------
// 4) Epilogue via tf32 tensor cores:
//    T[i,c] = x[bs,i,c] - d[i]*Z[i][bs*64+c]   (tf32, in SMEM)
//    out[bs,i,h] = sigmoid( T @ W^T )          (mma.sync m16n8k8 tf32)
//    grid (NN/128, BS), 256 threads = 8 warps, warp = 16 rows x 128 h
// ---------------------------------------------------------------------------
#define EP_PAD 68                     // row stride in u32 (64 + 4)
#define EPI_DYN ((128*EP_PAD + 128*EP_PAD) * 4)   // T + W, 69632 B

__global__ void __launch_bounds__(256) epilogue_kernel(const float* __restrict__ x,
                                                       const float* __restrict__ W,
                                                       float* __restrict__ out) {
    extern __shared__ __align__(16) u32 esm[];
    u32* sT = esm;                    // [128][EP_PAD] tf32
    u32* sW = esm + 128 * EP_PAD;     // [128][EP_PAD] tf32

    const int tid  = threadIdx.x;
    const int lane = tid & 31, wid = tid >> 5;
    const int i0   = blockIdx.x * 128;
    const int bs   = blockIdx.y;

    // Build W (tf32): 128 h x 64 c  = 2048 float4
    for (int k = tid; k < 2048; k += 256) {
        int h = k >> 4, c4 = k & 15;
        float4 v = reinterpret_cast<const float4*>(W)[(u64)h * 16 + c4];
        u32* d = sW + h * EP_PAD + c4 * 4;
        d[0] = f2tf32(v.x); d[1] = f2tf32(v.y); d[2] = f2tf32(v.z); d[3] = f2tf32(v.w);
    }
    // Build T (tf32): 128 i x 64 c = 2048 float4 (x) + uint2 (z)
    for (int k = tid; k < 2048; k += 256) {
        int r = k >> 4, c4 = k & 15;
        int i = i0 + r;
        float4 xv = reinterpret_cast<const float4*>(x)[((u64)bs * NN + i) * 16 + c4];
        uint2 zr = *reinterpret_cast<const uint2*>(g_z16 + (u64)i * PP + bs * CC + c4 * 4);
        __nv_bfloat162 zlo = *reinterpret_cast<__nv_bfloat162*>(&zr.x);
        __nv_bfloat162 zhi = *reinterpret_cast<__nv_bfloat162*>(&zr.y);
        float di = g_d[i];
        u32* d = sT + r * EP_PAD + c4 * 4;
        d[0] = f2tf32(xv.x - di * __bfloat162float(zlo.x));
        d[1] = f2tf32(xv.y - di * __bfloat162float(zlo.y));
        d[2] = f2tf32(xv.z - di * __bfloat162float(zhi.x));
        d[3] = f2tf32(xv.w - di * __bfloat162float(zhi.y));
    }
    __syncthreads();

    // Warp tile: rows [wid*16, wid*16+16), all 128 h (16 n8-tiles), K=64 in 8 steps
    const int gq = lane >> 2;          // 0..7
    const int tq = lane & 3;           // 0..3
    float acc[16][4];
    #pragma unroll
    for (int nt = 0; nt < 16; nt++)
        #pragma unroll
        for (int q = 0; q < 4; q++) acc[nt][q] = 0.f;

    const u32* tRow0 = sT + (wid * 16 + gq) * EP_PAD;
    const u32* tRow8 = tRow0 + 8 * EP_PAD;

    #pragma unroll
    for (int ks = 0; ks < 8; ks++) {
        int k0 = ks * 8 + tq;
        u32 a0 = tRow0[k0];
        u32 a1 = tRow8[k0];
        u32 a2 = tRow0[k0 + 4];
        u32 a3 = tRow8[k0 + 4];
        #pragma unroll
        for (int nt = 0; nt < 16; nt++) {
            const u32* wRow = sW + (nt * 8 + gq) * EP_PAD;
            u32 b0 = wRow[ks * 8 + tq];
            u32 b1 = wRow[ks * 8 + tq + 4];
            asm volatile("mma.sync.aligned.m16n8k8.row.col.f32.tf32.tf32.f32 "
                "{%0,%1,%2,%3}, {%4,%5,%6,%7}, {%8,%9}, {%0,%1,%2,%3};"
                : "+f"(acc[nt][0]), "+f"(acc[nt][1]), "+f"(acc[nt][2]), "+f"(acc[nt][3])
                : "r"(a0), "r"(a1), "r"(a2), "r"(a3), "r"(b0), "r"(b1));
        }
    }

    // sigmoid + store (each 32B sector fully covered by a lane quad)
    const int iA = i0 + wid * 16 + gq;
    float* oA = out + ((u64)bs * NN + iA) * HH + tq * 2;
    float* oB = oA + (u64)8 * HH;
    #pragma unroll
    for (int nt = 0; nt < 16; nt++) {
        float2 v0, v1;
        v0.x = 1.0f / (1.0f + __expf(-acc[nt][0]));
        v0.y = 1.0f / (1.0f + __expf(-acc[nt][1]));
        v1.x = 1.0f / (1.0f + __expf(-acc[nt][2]));
        v1.y = 1.0f / (1.0f + __expf(-acc[nt][3]));
        *reinterpret_cast<float2*>(oA + nt * 8) = v0;
        *reinterpret_cast<float2*>(oB + nt * 8) = v1;
    }
}

// ---------------------------------------------------------------------------
extern "C" void kernel_launch(void* const* d_in, const int* in_sizes, int n_in,
                              void* d_out, int out_size) {
    const float* x = (const float*)d_in[0];
    const float* A = (const float*)d_in[1];
    const float* W = (const float*)d_in[2];
    float* out = (float*)d_out;

    const int out_elems = NB * NS * NN * HH;   // 25,165,824
    const int do_copy = (out_size >= out_elems + NN * NN) ? 1 : 0;
    float* tail = do_copy ? (out + out_elems) : (float*)g_z16;

    cudaFuncSetAttribute(gemm1_kernel,
                         cudaFuncAttributeMaxDynamicSharedMemorySize, GEMM_DYN);
    cudaFuncSetAttribute(epilogue_kernel,
                         cudaFuncAttributeMaxDynamicSharedMemorySize, EPI_DYN);

    fusedA_kernel<<<NN, 256>>>(A, tail, do_copy);

    {
        dim3 grid(NN / 64, BS);          // (64, 48)
        build_xdT_kernel<<<grid, 256>>>(x);
    }
    {
        dim3 grid(PP / 128, NN / 128);   // (24, 32)
        gemm1_kernel<<<grid, 256, GEMM_DYN>>>();
    }
    {
        dim3 grid(NN / 128, BS);         // (32, 48)
        epilogue_kernel<<<grid, 256, EPI_DYN>>>(x, W, out);
    }
}